// round 8
// baseline (speedup 1.0000x reference)
#include <cuda_runtime.h>
#include <cstdint>

#define EDIM   4096
#define BATCH  128
#define NHEAD  32
#define HDIM   128
#define WIN    128
#define TOPK   96

// Scratch (device globals: allocation-free)
__device__ float    g_q[BATCH * EDIM];
__device__ float    g_k[BATCH * EDIM];
__device__ float    g_v[BATCH * EDIM];
__device__ uint32_t g_xh[BATCH * EDIM / 2];   // x split hi (bf16x2)
__device__ uint32_t g_xl[BATCH * EDIM / 2];   // x split lo
__device__ uint32_t g_ch[BATCH * EDIM / 2];   // consensus hi
__device__ uint32_t g_cl[BATCH * EDIM / 2];   // consensus lo

__device__ __forceinline__ uint32_t smem_u32(const void* p) {
    return (uint32_t)__cvta_generic_to_shared(p);
}
__device__ __forceinline__ void cp16a(uint32_t smem, const void* gmem) {
    asm volatile("cp.async.cg.shared.global [%0], [%1], 16;\n"
                 :: "r"(smem), "l"(gmem));
}

// Split a float2 into packed bf16x2 hi and lo terms: f = hi + lo (each bf16).
__device__ __forceinline__ void split2(float2 f, uint32_t& hi, uint32_t& lo) {
    uint32_t h;
    asm("cvt.rn.bf16x2.f32 %0, %1, %2;" : "=r"(h) : "f"(f.y), "f"(f.x));
    float h0 = __uint_as_float(h << 16);
    float h1 = __uint_as_float(h & 0xffff0000u);
    float r0 = f.x - h0;
    float r1 = f.y - h1;
    uint32_t l;
    asm("cvt.rn.bf16x2.f32 %0, %1, %2;" : "=r"(l) : "f"(r1), "f"(r0));
    hi = h; lo = l;
}

__device__ __forceinline__ void mma_bf16(float c[4], const uint32_t a[4],
                                         uint32_t b0, uint32_t b1) {
    asm volatile(
        "mma.sync.aligned.m16n8k16.row.col.f32.bf16.bf16.f32 "
        "{%0,%1,%2,%3}, {%4,%5,%6,%7}, {%8,%9}, {%0,%1,%2,%3};\n"
        : "+f"(c[0]), "+f"(c[1]), "+f"(c[2]), "+f"(c[3])
        : "r"(a[0]), "r"(a[1]), "r"(a[2]), "r"(a[3]), "r"(b0), "r"(b1));
}

__device__ __forceinline__ void ldsm4(uint32_t* d, uint32_t addr) {
    asm volatile("ldmatrix.sync.aligned.m8n8.x4.shared.b16 {%0,%1,%2,%3}, [%4];"
                 : "=r"(d[0]), "=r"(d[1]), "=r"(d[2]), "=r"(d[3]) : "r"(addr));
}
__device__ __forceinline__ float2 lds64(uint32_t addr) {
    float2 v;
    asm volatile("ld.shared.v2.f32 {%0,%1}, [%2];"
                 : "=f"(v.x), "=f"(v.y) : "r"(addr));
    return v;
}

// ---------------------------------------------------------------------------
// Prep: convert x -> bf16 hi/lo; init g_q/g_k/g_v with biases; init out w/ bo.
// ---------------------------------------------------------------------------
__global__ void prep_kernel(const float* __restrict__ x,
                            const float* __restrict__ bq,
                            const float* __restrict__ bk,
                            const float* __restrict__ bv,
                            const float* __restrict__ bo,
                            float* __restrict__ out) {
    int i = blockIdx.x * 256 + threadIdx.x;          // < 524288
    int n = i & (EDIM - 1);
    g_q[i] = bq[n]; g_k[i] = bk[n]; g_v[i] = bv[n];
    out[i] = bo[n];
    if (i < BATCH * EDIM / 2) {
        float2 f = ((const float2*)x)[i];
        uint32_t h, l; split2(f, h, l);
        g_xh[i] = h; g_xl[i] = l;
    }
}

// ---------------------------------------------------------------------------
// GEMM: out[128, 64-tile] += A[128, GK] @ W[64-tile, GK]^T
// A pre-split bf16 hi/lo (cp.async, swizzled, ldmatrix consumer).
// W streamed as RAW fp32 via cp.async (4-deep ring); hi/lo split happens in
// the consumer (LDS.64 + split2 per B fragment) -- no STS, no W LDG-reg path.
// BK=32/stage, 32 stages, split-K=4, atomicAdd epilogue (bias pre-filled).
// Ring buffer (24576 B/stage x 4):  Ah[128][64B] @0, Al @8192, Wf32[64][128B] @16384
// A swizzle: 16B chunk c of row r at (c ^ ((r>>1)&3)); W: (c ^ (r&7)).
// Warps: 2m x 4n; per warp m64 (4 m16 tiles) x n16 (2 n8 tiles).
// ---------------------------------------------------------------------------
#define GK 1024
#define GT 32     // GK/32 stages
#define STG 24576

__device__ __forceinline__ void gemm_body(const uint32_t* __restrict__ Ah_g,
                                          const uint32_t* __restrict__ Al_g,
                                          const float* __restrict__ Wt,
                                          float* __restrict__ out,
                                          char* smem) {
    const int tid  = threadIdx.x;
    const int lane = tid & 31;
    const int warp = tid >> 5;
    const int n0   = blockIdx.x * 64;
    const int k0   = blockIdx.y * GK;
    const int k0w  = k0 >> 1;
    const int wm   = warp >> 2;          // 0..1  (m64 tiles)
    const int wn   = warp & 3;           // 0..3  (n16 tiles)
    const int rql  = lane >> 2;          // 0..7
    const int kq   = lane & 3;
    const uint32_t s0 = smem_u32(smem);

    float c[4][2][4];
#pragma unroll
    for (int i = 0; i < 4; i++)
#pragma unroll
        for (int j = 0; j < 2; j++)
#pragma unroll
            for (int q = 0; q < 4; q++) c[i][j][q] = 0.f;

    // Producer mappings
    const int arow = tid >> 1;            // 0..127
    const int acb  = (tid & 1) * 2;       // A chunk pair {0,1} or {2,3}
    const int wrow = tid >> 2;            // 0..63
    const int wcb  = (tid & 3) * 2;       // W chunk pair

    auto issue = [&](int t) {
        const uint32_t base = s0 + (t & 3) * STG;
#pragma unroll
        for (int ci = 0; ci < 2; ci++) {
            const int cA = acb + ci;
            const uint32_t doff = (uint32_t)(arow * 64 + 16 * (cA ^ ((arow >> 1) & 3)));
            const size_t soff = (size_t)arow * 2048 + k0w + t * 16 + cA * 4;
            cp16a(base + doff, Ah_g + soff);
            cp16a(base + 8192 + doff, Al_g + soff);
            const int cW = wcb + ci;
            const uint32_t wd = (uint32_t)(wrow * 128 + 16 * (cW ^ (wrow & 7)));
            cp16a(base + 16384 + wd,
                  Wt + (size_t)(n0 + wrow) * EDIM + k0 + t * 32 + cW * 4);
        }
        asm volatile("cp.async.commit_group;\n" ::);
    };

    // Consumer constants
    const int rA  = (lane & 15);          // A row within m16-pair
    const int hbA = lane >> 4;            // A k-half bit

    auto compute = [&](int t) {
        const uint32_t base  = s0 + (t & 3) * STG;
        const uint32_t wbase = base + 16384;
#pragma unroll
        for (int ch = 0; ch < 2; ch++) {
            uint32_t ah[4][4], al[4][4];
#pragma unroll
            for (int mt = 0; mt < 4; mt++) {
                const int row = wm * 64 + mt * 16 + rA;
                const int cc  = (2 * ch + hbA) ^ ((row >> 1) & 3);
                const uint32_t addr = base + row * 64 + cc * 16;
                ldsm4(ah[mt], addr);
                ldsm4(al[mt], addr + 8192);
            }
#pragma unroll
            for (int nt = 0; nt < 2; nt++) {
                const int n  = wn * 16 + nt * 8 + rql;
                const int c0 = (ch * 4 + (kq >> 1)) ^ (n & 7);
                const int c1 = (ch * 4 + (kq >> 1) + 2) ^ (n & 7);
                const uint32_t rb = wbase + n * 128 + (kq & 1) * 8;
                float2 f0 = lds64(rb + c0 * 16);
                float2 f1 = lds64(rb + c1 * 16);
                uint32_t b0h, b0l, b1h, b1l;
                split2(f0, b0h, b0l);
                split2(f1, b1h, b1l);
#pragma unroll
                for (int mt = 0; mt < 4; mt++) {
                    mma_bf16(c[mt][nt], ah[mt], b0h, b1h);
                    mma_bf16(c[mt][nt], ah[mt], b0l, b1l);
                    mma_bf16(c[mt][nt], al[mt], b0h, b1h);
                }
            }
        }
    };

    // Prologue: fill 3 stages
    issue(0); issue(1); issue(2);
    asm volatile("cp.async.wait_group 2;\n" ::);
    __syncthreads();

    for (int t = 0; t < GT; t++) {
        if (t + 3 < GT) issue(t + 3);
        compute(t);
        if (t < GT - 3) {
            asm volatile("cp.async.wait_group 2;\n" ::);
        } else {
            asm volatile("cp.async.wait_group 0;\n" ::);
        }
        __syncthreads();
    }

    // Epilogue: atomic accumulate (bias pre-filled by prep kernel)
#pragma unroll
    for (int mt = 0; mt < 4; mt++) {
        const int row = wm * 64 + mt * 16 + rql;
#pragma unroll
        for (int nt = 0; nt < 2; nt++) {
            const int n = n0 + wn * 16 + nt * 8 + 2 * kq;
            atomicAdd(&out[(size_t)row * EDIM + n],           c[mt][nt][0]);
            atomicAdd(&out[(size_t)row * EDIM + n + 1],       c[mt][nt][1]);
            atomicAdd(&out[(size_t)(row + 8) * EDIM + n],     c[mt][nt][2]);
            atomicAdd(&out[(size_t)(row + 8) * EDIM + n + 1], c[mt][nt][3]);
        }
    }
}

__global__ void __launch_bounds__(256, 2) qkv_gemm(const float* __restrict__ Wq,
                                                   const float* __restrict__ Wk,
                                                   const float* __restrict__ Wv) {
    extern __shared__ char sm[];
    const float* W; float* out;
    if (blockIdx.z == 0)      { W = Wq; out = g_q; }
    else if (blockIdx.z == 1) { W = Wk; out = g_k; }
    else                      { W = Wv; out = g_v; }
    gemm_body(g_xh, g_xl, W, out, sm);
}

__global__ void __launch_bounds__(256, 2) out_gemm(const float* __restrict__ Wo,
                                                   float* __restrict__ out) {
    extern __shared__ char sm[];
    gemm_body(g_ch, g_cl, Wo, out, sm);
}

// ---------------------------------------------------------------------------
// Fused ring-write + copy-out + RBF attention, streaming (at LTS cap).
// ---------------------------------------------------------------------------
__global__ void __launch_bounds__(512) attn_kernel(
    const float* __restrict__ K_ring, const float* __restrict__ V_ring,
    const float* __restrict__ log_sigma, const int* __restrict__ curpos,
    float* __restrict__ out_base) {
    __shared__ float  qs[HDIM];
    __shared__ float  sc[WIN];
    __shared__ float  pv[WIN];
    __shared__ float  red[8];
    __shared__ float4 part4[16 * 32];

    const int bh   = blockIdx.x;
    const int b    = bh >> 5;
    const int h    = bh & 31;
    const int tid  = threadIdx.x;
    const int lane = tid & 31;
    const int wp   = tid >> 5;
    const int idx  = curpos[0] & (WIN - 1);

    const size_t base  = (size_t)bh * (WIN * HDIM);
    const size_t OUT_O = (size_t)BATCH * EDIM;
    const size_t SEG   = (size_t)BATCH * NHEAD * WIN * HDIM;

    const float4* Ksrc  = (const float4*)(K_ring + base);
    const float4* Vsrc  = (const float4*)(V_ring + base);
    float4* Kout        = (float4*)(out_base + OUT_O + base);
    float4* Vout        = (float4*)(out_base + OUT_O + SEG + base);
    const float4* knew4 = (const float4*)(g_k + (size_t)b * EDIM + h * HDIM);
    const float4* vnew4 = (const float4*)(g_v + (size_t)b * EDIM + h * HDIM);

    if (tid < HDIM) qs[tid] = g_q[(size_t)b * EDIM + h * HDIM + tid];
    __syncthreads();

    const float inv = -0.5f * expf(-2.0f * log_sigma[h]);

    // ---- K pass: copy + inline squared distance (warp owns row w) ----
#pragma unroll
    for (int j = 0; j < 8; j++) {
        const int i = tid + j * 512;
        const int w = i >> 5;
        float4 val = (w == idx) ? knew4[lane] : Ksrc[i];
        Kout[i] = val;
        float d0 = val.x - qs[lane * 4 + 0];
        float d1 = val.y - qs[lane * 4 + 1];
        float d2 = val.z - qs[lane * 4 + 2];
        float d3 = val.w - qs[lane * 4 + 3];
        float ss = d0 * d0 + d1 * d1 + d2 * d2 + d3 * d3;
#pragma unroll
        for (int o = 16; o; o >>= 1) ss += __shfl_xor_sync(0xffffffffu, ss, o);
        if (lane == 0) sc[w] = ss * inv;
    }
    __syncthreads();

    // ---- top-96 selection + softmax ----
    float s = 0.f, e = 0.f;
    bool sel = false;
    if (tid < WIN) {
        s = sc[tid];
        int cnt = 0;
#pragma unroll 8
        for (int j = 0; j < WIN; j++) {
            float o2 = sc[j];
            cnt += (o2 > s) || (o2 == s && j < tid);
        }
        sel = (cnt < TOPK);
        float mm = s;
#pragma unroll
        for (int o = 16; o; o >>= 1)
            mm = fmaxf(mm, __shfl_xor_sync(0xffffffffu, mm, o));
        if (lane == 0) red[wp] = mm;
    }
    __syncthreads();
    const float m = fmaxf(fmaxf(red[0], red[1]), fmaxf(red[2], red[3]));
    if (tid < WIN) {
        e = sel ? expf(s - m) : 0.f;
        float z = e;
#pragma unroll
        for (int o = 16; o; o >>= 1) z += __shfl_xor_sync(0xffffffffu, z, o);
        if (lane == 0) red[4 + wp] = z;
    }
    __syncthreads();
    if (tid < WIN) pv[tid] = e / (red[4] + red[5] + red[6] + red[7]);
    __syncthreads();

    // ---- V pass: copy + inline weighted accumulation ----
    float4 acc = make_float4(0.f, 0.f, 0.f, 0.f);
#pragma unroll
    for (int j = 0; j < 8; j++) {
        const int i = tid + j * 512;
        const int w = i >> 5;
        float4 val = (w == idx) ? vnew4[lane] : Vsrc[i];
        Vout[i] = val;
        const float p = pv[w];
        acc.x += p * val.x; acc.y += p * val.y;
        acc.z += p * val.z; acc.w += p * val.w;
    }
    part4[wp * 32 + lane] = acc;
    __syncthreads();

    // ---- cross-warp reduce + write consensus as bf16 hi/lo ----
    if (tid < HDIM) {
        const float* pf = (const float*)part4;
        float a = 0.f;
#pragma unroll
        for (int w2 = 0; w2 < 16; w2++) a += pf[w2 * 128 + tid];
        float o = __shfl_xor_sync(0xffffffffu, a, 1);
        if ((tid & 1) == 0) {
            uint32_t hh, ll;
            split2(make_float2(a, o), hh, ll);
            const int wi = bh * 64 + (tid >> 1);
            g_ch[wi] = hh; g_cl[wi] = ll;
        }
    }
}

// ---------------------------------------------------------------------------
extern "C" void kernel_launch(void* const* d_in, const int* in_sizes, int n_in,
                              void* d_out, int out_size) {
    const float* x      = (const float*)d_in[0];
    const float* Wq     = (const float*)d_in[1];
    const float* bq     = (const float*)d_in[2];
    const float* Wk     = (const float*)d_in[3];
    const float* bk     = (const float*)d_in[4];
    const float* Wv     = (const float*)d_in[5];
    const float* bv     = (const float*)d_in[6];
    const float* Wo     = (const float*)d_in[7];
    const float* bo     = (const float*)d_in[8];
    const float* ls     = (const float*)d_in[9];
    const float* K_ring = (const float*)d_in[10];
    const float* V_ring = (const float*)d_in[11];
    const int*   cpos   = (const int*)d_in[12];
    float* out = (float*)d_out;

    const int gemm_smem = 4 * STG;   // 98304 B
    cudaFuncSetAttribute(qkv_gemm, cudaFuncAttributeMaxDynamicSharedMemorySize, gemm_smem);
    cudaFuncSetAttribute(out_gemm, cudaFuncAttributeMaxDynamicSharedMemorySize, gemm_smem);

    prep_kernel<<<2048, 256>>>(x, bq, bk, bv, bo, out);

    qkv_gemm<<<dim3(64, 4, 3), 256, gemm_smem>>>(Wq, Wk, Wv);

    attn_kernel<<<BATCH * NHEAD, 512>>>(K_ring, V_ring, ls, cpos, out);

    out_gemm<<<dim3(64, 4, 1), 256, gemm_smem>>>(Wo, out);
}